// round 2
// baseline (speedup 1.0000x reference)
#include <cuda_runtime.h>
#include <cstdint>

// ---------------------------------------------------------------------------
// GCN message-passing layer:
//   agg[d] += x[s] for each edge (s,d)      (segment sum)
//   out    = relu(agg @ W^T) + x            (linear, bias-free, + residual)
// Shapes: x [N,64] f32, W [64,64] f32 (row-major, [out][in]), src/dst [E] i32
// ---------------------------------------------------------------------------

#define D 64            // feature dim (in == out == 64)
#define D4 (D / 4)      // 16 float4 per row
#define MAX_NODES 50000

// Scratch: aggregated neighbor features. __device__ global (no allocs allowed).
__device__ float4 g_agg[MAX_NODES * D4];

// ---------------------------------------------------------------------------
// Kernel 1: zero the aggregation buffer
// ---------------------------------------------------------------------------
__global__ void zero_agg_kernel(int n_vec4) {
    int i = blockIdx.x * blockDim.x + threadIdx.x;
    if (i < n_vec4) {
        g_agg[i] = make_float4(0.f, 0.f, 0.f, 0.f);
    }
}

// ---------------------------------------------------------------------------
// Kernel 2: edge scatter. One thread per (edge, 16B-chunk): 16 threads/edge.
// Consecutive threads cover consecutive float4 of the same source row ->
// fully coalesced 256B row reads; vectorized red.global.add.v4.f32 for the
// accumulation (no return value, 4x fewer atomic ops than scalar atomicAdd).
// ---------------------------------------------------------------------------
__global__ void scatter_kernel(const float4* __restrict__ x4,
                               const int* __restrict__ src,
                               const int* __restrict__ dst,
                               int n_edges) {
    long gid = (long)blockIdx.x * blockDim.x + threadIdx.x;
    int e    = (int)(gid >> 4);      // edge index
    int lane = (int)(gid & 15);      // which float4 of the 64-float row
    if (e >= n_edges) return;

    int s = src[e];
    int d = dst[e];

    float4 v = x4[(long)s * D4 + lane];
    float4* p = &g_agg[(long)d * D4 + lane];

    asm volatile("red.global.add.v4.f32 [%0], {%1, %2, %3, %4};"
                 :: "l"(p), "f"(v.x), "f"(v.y), "f"(v.z), "f"(v.w)
                 : "memory");
}

// ---------------------------------------------------------------------------
// Kernel 3: fused GEMM + ReLU + residual.
// One thread per node. W (16 KB) staged in shared memory; every thread in a
// warp reads the same W element -> LDS broadcast (conflict-free).
// agg row held in 16 float4 registers.
// ---------------------------------------------------------------------------
__global__ void __launch_bounds__(128)
gemm_relu_res_kernel(const float* __restrict__ W,
                     const float4* __restrict__ x4,
                     float4* __restrict__ out4,
                     int n_nodes) {
    __shared__ float4 Ws[D][D4];   // W[o][k] as float4 chunks

    // Cooperative load of W: 64*16 = 1024 float4 entries, 128 threads
    const float4* W4 = (const float4*)W;
    for (int i = threadIdx.x; i < D * D4; i += blockDim.x) {
        Ws[i / D4][i % D4] = W4[i];
    }
    __syncthreads();

    int n = blockIdx.x * blockDim.x + threadIdx.x;
    if (n >= n_nodes) return;

    // Load aggregated row into registers
    float4 a[D4];
#pragma unroll
    for (int k = 0; k < D4; k++) {
        a[k] = g_agg[(long)n * D4 + k];
    }

    // 64 dot products of length 64, fused relu + residual, vectorized stores
#pragma unroll
    for (int og = 0; og < D4; og++) {
        float4 r;
        float* rp = &r.x;
#pragma unroll
        for (int j = 0; j < 4; j++) {
            int o = og * 4 + j;
            float acc = 0.f;
#pragma unroll
            for (int k = 0; k < D4; k++) {
                float4 w = Ws[o][k];
                acc = fmaf(a[k].x, w.x, acc);
                acc = fmaf(a[k].y, w.y, acc);
                acc = fmaf(a[k].z, w.z, acc);
                acc = fmaf(a[k].w, w.w, acc);
            }
            rp[j] = fmaxf(acc, 0.f);
        }
        float4 xr = x4[(long)n * D4 + og];
        r.x += xr.x; r.y += xr.y; r.z += xr.z; r.w += xr.w;
        out4[(long)n * D4 + og] = r;
    }
}

// ---------------------------------------------------------------------------
// Launch
// ---------------------------------------------------------------------------
extern "C" void kernel_launch(void* const* d_in, const int* in_sizes, int n_in,
                              void* d_out, int out_size) {
    const float* x   = (const float*)d_in[0];   // [N, 64]
    const float* W   = (const float*)d_in[1];   // [64, 64]
    const int*   src = (const int*)d_in[2];     // [E]
    const int*   dst = (const int*)d_in[3];     // [E]
    float*       out = (float*)d_out;           // [N, 64]

    int n_nodes = in_sizes[0] / D;
    int n_edges = in_sizes[2];

    const float4* x4   = (const float4*)x;
    float4*       out4 = (float4*)out;

    // 1) zero agg
    {
        int n_vec4 = n_nodes * D4;
        int threads = 256;
        int blocks = (n_vec4 + threads - 1) / threads;
        zero_agg_kernel<<<blocks, threads>>>(n_vec4);
    }

    // 2) scatter edges
    {
        long total = (long)n_edges * 16;
        int threads = 256;
        int blocks = (int)((total + threads - 1) / threads);
        scatter_kernel<<<blocks, threads>>>(x4, src, dst, n_edges);
    }

    // 3) fused gemm + relu + residual
    {
        int threads = 128;
        int blocks = (n_nodes + threads - 1) / threads;
        gemm_relu_res_kernel<<<blocks, threads>>>(W, x4, out4, n_nodes);
    }
}